// round 15
// baseline (speedup 1.0000x reference)
#include <cuda_runtime.h>
#include <cuda_fp16.h>
#include <cstdint>

// ---------------- problem sizes ----------------
static constexpr int M_TOTAL = 32768;   // B*S = 4*8192
static constexpr int K_TOTAL = 1024;    // I
static constexpr int N_TOTAL = 1024;    // O
static constexpr int TILE_M  = 128;
static constexpr int TILE_N  = 256;
static constexpr int TILE_K  = 64;
static constexpr int NUM_KC  = K_TOTAL / TILE_K;        // 16
static constexpr int M_TILES = M_TOTAL / TILE_M;        // 256
static constexpr int N_TILES = N_TOTAL / TILE_N;        // 4
static constexpr int NTILES_TOTAL = M_TILES * N_TILES;  // 1024
static constexpr int A_STAGE = TILE_M * TILE_K * 2;     // 16384
static constexpr int B_STAGE = TILE_N * TILE_K * 2;     // 32768
static constexpr int STAGES  = 4;
static constexpr int SMEM_TOTAL = STAGES * (A_STAGE + B_STAGE); // 196608
static constexpr int GRID_SMS = 152;    // GB300 SM count -> persistent 1 CTA/SM

// ---------------- device scratch ----------------
__device__ __align__(16) __half g_wh[(size_t)N_TOTAL * K_TOTAL]; // 2 MiB ternary W f16 row-major
__device__ double g_partial[256];
__device__ float  g_thr;

// ---------------- helpers ----------------
__device__ __forceinline__ uint32_t smem_u32(const void* p) {
    uint32_t a;
    asm("{ .reg .u64 t; cvta.to.shared.u64 t, %1; cvt.u32.u64 %0, t; }" : "=r"(a) : "l"(p));
    return a;
}
__device__ __forceinline__ uint32_t sw128(uint32_t off) { return off ^ ((off >> 3) & 0x70); }

__device__ __forceinline__ void cp_async16(uint32_t smem_addr, const void* gptr) {
    asm volatile("cp.async.cg.shared.global [%0], [%1], 16;"
                 :: "r"(smem_addr), "l"(gptr) : "memory");
}
#define CP_COMMIT() asm volatile("cp.async.commit_group;" ::: "memory")
#define CP_WAIT(n)  asm volatile("cp.async.wait_group %0;" :: "n"(n) : "memory")

__device__ __forceinline__ void ldmatrix_x4(uint32_t* r, uint32_t addr) {
    asm volatile("ldmatrix.sync.aligned.m8n8.x4.shared.b16 {%0,%1,%2,%3}, [%4];"
                 : "=r"(r[0]), "=r"(r[1]), "=r"(r[2]), "=r"(r[3]) : "r"(addr));
}
__device__ __forceinline__ void mma16816(float* d, const uint32_t* a, const uint32_t* b) {
    asm volatile(
        "mma.sync.aligned.m16n8k16.row.col.f32.f16.f16.f32 "
        "{%0,%1,%2,%3}, {%4,%5,%6,%7}, {%8,%9}, {%0,%1,%2,%3};"
        : "+f"(d[0]), "+f"(d[1]), "+f"(d[2]), "+f"(d[3])
        : "r"(a[0]), "r"(a[1]), "r"(a[2]), "r"(a[3]), "r"(b[0]), "r"(b[1]));
}
__device__ __forceinline__ void sts64(uint32_t addr, uint32_t v0, uint32_t v1) {
    asm volatile("st.shared.v2.b32 [%0], {%1,%2};" :: "r"(addr), "r"(v0), "r"(v1) : "memory");
}
__device__ __forceinline__ void stg_cs_v2(float* p, float a, float b) {
    asm volatile("st.global.cs.v2.f32 [%0], {%1,%2};" :: "l"(p), "f"(a), "f"(b) : "memory");
}
// 32B x-load with L2::evict_last (legal shape on this ptxas: .v4.b64).
__device__ __forceinline__ void ldg_el_32B(const float* p, float4& lo, float4& hi) {
    unsigned long long r0, r1, r2, r3;
    asm volatile("ld.global.nc.L2::evict_last.v4.b64 {%0,%1,%2,%3}, [%4];"
                 : "=l"(r0), "=l"(r1), "=l"(r2), "=l"(r3) : "l"(p));
    lo.x = __uint_as_float((uint32_t)r0);  lo.y = __uint_as_float((uint32_t)(r0 >> 32));
    lo.z = __uint_as_float((uint32_t)r1);  lo.w = __uint_as_float((uint32_t)(r1 >> 32));
    hi.x = __uint_as_float((uint32_t)r2);  hi.y = __uint_as_float((uint32_t)(r2 >> 32));
    hi.z = __uint_as_float((uint32_t)r3);  hi.w = __uint_as_float((uint32_t)(r3 >> 32));
}
__device__ __forceinline__ uint32_t f2h2(float a, float b) {
    __half2 h = __floats2half2_rn(a, b);
    return *reinterpret_cast<uint32_t*>(&h);
}

// ---------------- kernel 0: partial |W| sums (deterministic) --------------
__global__ void absrow_kernel(const float* __restrict__ W) {
    __shared__ double sred[256];
    const float4* p = (const float4*)W + blockIdx.x * 1024 + threadIdx.x;
    float s = 0.0f;
    #pragma unroll
    for (int i = 0; i < 4; i++) {
        float4 f = p[i * 256];
        s += fabsf(f.x) + fabsf(f.y) + fabsf(f.z) + fabsf(f.w);
    }
    sred[threadIdx.x] = (double)s;
    __syncthreads();
    for (int off = 128; off > 0; off >>= 1) {
        if (threadIdx.x < off) sred[threadIdx.x] += sred[threadIdx.x + off];
        __syncthreads();
    }
    if (threadIdx.x == 0) g_partial[blockIdx.x] = sred[0];
}

// ---------------- kernel 1: alpha -> g_thr (one block, fixed tree) --------
__global__ void alpha_kernel() {
    __shared__ double sred[256];
    sred[threadIdx.x] = g_partial[threadIdx.x];
    __syncthreads();
    for (int off = 128; off > 0; off >>= 1) {
        if (threadIdx.x < off) sred[threadIdx.x] += sred[threadIdx.x + off];
        __syncthreads();
    }
    if (threadIdx.x == 0) {
        float alpha = (float)(sred[0] / ((double)N_TOTAL * (double)K_TOTAL));
        g_thr = alpha * 0.5f;
    }
}

// ---------------- kernel 2: ternarize W -> f16 row-major -------------------
__global__ void ternarize_kernel(const float* __restrict__ W) {
    float t = g_thr;
    int idx = blockIdx.x * blockDim.x + threadIdx.x;
    if (idx >= N_TOTAL * K_TOTAL / 8) return;
    const float4* src = (const float4*)W + idx * 2;
    uint32_t h[4];
    #pragma unroll
    for (int v = 0; v < 2; v++) {
        float4 f = src[v];
        float q0 = (fabsf(f.x) > t) ? (f.x > 0.f ? 1.f : -1.f) : 0.f;
        float q1 = (fabsf(f.y) > t) ? (f.y > 0.f ? 1.f : -1.f) : 0.f;
        float q2 = (fabsf(f.z) > t) ? (f.z > 0.f ? 1.f : -1.f) : 0.f;
        float q3 = (fabsf(f.w) > t) ? (f.w > 0.f ? 1.f : -1.f) : 0.f;
        h[v * 2]     = f2h2(q0, q1);
        h[v * 2 + 1] = f2h2(q2, q3);
    }
    ((uint4*)g_wh)[idx] = make_uint4(h[0], h[1], h[2], h[3]);
}

// ---------------- kernel 3: PERSISTENT fused-convert f16 mma.sync GEMM ----
// R14 engine; chunk-head order refined: kk0 fragment LDSMs go FIRST after
// the barrier (time-to-first-MMA is the exposed path), then B cp.asyncs
// (5800cyc slack), then the A-producer LDG batch.
__global__ void __launch_bounds__(256, 1) gemm_kernel(const float* __restrict__ bias,
                                                      const float* __restrict__ x,
                                                      float* __restrict__ out) {
    extern __shared__ char smem[];
    const int tid = threadIdx.x, lane = tid & 31, wid = tid >> 5;
    const int warp_m = wid & 1;        // 2 warps along M (64 rows)
    const int warp_n = wid >> 1;       // 4 warps along N (64 cols)

    const uint32_t sA = smem_u32(smem);
    const uint32_t sB = sA + STAGES * A_STAGE;

    // ---- affine producer mappings (tile-invariant parts) ----
    const int a_c8 = tid & 7;               // 32B column within 256B fp32 row
    const int a_r0 = tid >> 3;              // 0..31
    const uint32_t a_smem0 = sw128((uint32_t)(a_r0 * 128 + a_c8 * 16)); // +i*4096 swizzle-safe
    const int b_c8 = tid & 7;
    const int b_r0 = tid >> 3;
    const uint32_t b_smem0 = sw128((uint32_t)(b_r0 * 128 + b_c8 * 16)); // +i*4096 swizzle-safe
    const int GROWB = K_TOTAL * 2;

    auto a_base = [&](int t) {
        return x + (size_t)(((t >> 2) * TILE_M) + a_r0) * K_TOTAL + a_c8 * 8;
    };
    auto b_base = [&](int t) {
        return (const char*)(g_wh + (size_t)(((t & 3) * TILE_N) + b_r0) * K_TOTAL) + b_c8 * 16;
    };

    auto issue_B = [&](const char* base, int pc, int s) {
        uint32_t dB = sB + s * B_STAGE + b_smem0;
        const char* srcB = base + pc * (TILE_K * 2);
        #pragma unroll
        for (int i = 0; i < 8; i++)
            cp_async16(dB + i * 4096, srcB + (size_t)i * 32 * GROWB);
        CP_COMMIT();
    };
    auto ldg_A = [&](const float* base, int pc, float4* buf) {
        const float* srcA = base + pc * TILE_K;
        #pragma unroll
        for (int i = 0; i < 4; i++)   // rows a_r0 + 32*i, one 32B load each
            ldg_el_32B(srcA + (size_t)i * 32 * K_TOTAL, buf[i * 2], buf[i * 2 + 1]);
    };
    auto sts_A = [&](int s, const float4* buf) {
        uint32_t dA = sA + s * A_STAGE + a_smem0;
        #pragma unroll
        for (int i = 0; i < 4; i++) {
            sts64(dA + i * 4096,     f2h2(buf[i*2].x, buf[i*2].y), f2h2(buf[i*2].z, buf[i*2].w));
            sts64(dA + i * 4096 + 8, f2h2(buf[i*2+1].x, buf[i*2+1].y), f2h2(buf[i*2+1].z, buf[i*2+1].w));
        }
    };

    // ---- persistent tile bookkeeping ----
    int t = blockIdx.x;                              // current tile
    int pft = t;                                     // tile owning prefetch targets
    const float* pfA = a_base(pft);
    const char*  pfB = b_base(pft);
    const int ntiles = (NTILES_TOTAL - blockIdx.x + GRID_SMS - 1) / GRID_SMS;
    const int total = ntiles * NUM_KC;

    // prologue: chunks 0,1 (lookahead 2) — paid ONCE per CTA
    issue_B(pfB, 0, 0); issue_B(pfB, 1, 1);
    {
        float4 pbuf[8];
        ldg_A(pfA, 0, pbuf); sts_A(0, pbuf);
        ldg_A(pfA, 1, pbuf); sts_A(1, pbuf);
    }

    float acc[4][8][4];
    #pragma unroll
    for (int i = 0; i < 4; i++)
        #pragma unroll
        for (int j = 0; j < 8; j++)
            #pragma unroll
            for (int v = 0; v < 4; v++) acc[i][j][v] = 0.f;

    // ldmatrix lane-address components
    const int a_row = warp_m * 64 + (lane & 15);
    const int a_kof = (lane >> 4) * 8;
    const int b_lrow = warp_n * 64 + (lane & 7) + ((lane >> 4) << 3);
    const int b_kof = ((lane >> 3) & 1) * 8;

    for (int k = 0; k < total; k++) {
        const int c = k & 15;
        if ((k & 1) == 0) {            // barrier every 2nd global chunk
            CP_WAIT(0);
            __syncthreads();
        }

        if (c == 14) {                 // prefetch crosses into next tile
            pft += GRID_SMS;
            if (pft >= NTILES_TOTAL) pft = 0;   // keep pointers valid; unused (pf=false)
            pfA = a_base(pft);
            pfB = b_base(pft);
        }

        const int pk = k + 2;
        const bool pf = (pk < total);
        const int pc = pk & 15;

        const uint32_t aT = sA + (k & 3) * A_STAGE;
        const uint32_t bT = sB + (k & 3) * B_STAGE;

        // 1) kk=0 fragments FIRST — shortest path to the first MMA
        uint32_t af[4][4], bf[4][4];
        #pragma unroll
        for (int ms = 0; ms < 4; ms++)
            ldmatrix_x4(af[ms], aT + sw128((uint32_t)((a_row + ms * 16) * 128 + a_kof * 2)));
        #pragma unroll
        for (int ns2 = 0; ns2 < 4; ns2++)
            ldmatrix_x4(bf[ns2], bT + sw128((uint32_t)((b_lrow + ns2 * 16) * 128 + b_kof * 2)));

        // 2) B prefetch (fire-and-forget; ~2 chunks of slack)
        if (pf) issue_B(pfB, pc, pk & 3);

        // 3) A producer LDG batch (independent; overlaps kk=0 MMAs)
        float4 buf[8];
        if (pf) ldg_A(pfA, pc, buf);

        #pragma unroll
        for (int kk = 0; kk < 4; kk++) {
            #pragma unroll
            for (int ms = 0; ms < 4; ms++)
                #pragma unroll
                for (int ns = 0; ns < 8; ns++)
                    mma16816(acc[ms][ns], af[ms], bf[ns >> 1] + (ns & 1) * 2);

            if (kk == 2 && pf)
                sts_A(pk & 3, buf);    // kk==2: ~1560cyc slack for the A LDGs

            if (kk < 3) {              // fragments for kk+1 (same registers)
                #pragma unroll
                for (int ms = 0; ms < 4; ms++)
                    ldmatrix_x4(af[ms], aT + sw128((uint32_t)((a_row + ms * 16) * 128 +
                                                              ((kk + 1) * 16 + a_kof) * 2)));
                #pragma unroll
                for (int ns2 = 0; ns2 < 4; ns2++)
                    ldmatrix_x4(bf[ns2], bT + sw128((uint32_t)((b_lrow + ns2 * 16) * 128 +
                                                               ((kk + 1) * 16 + b_kof) * 2)));
            }
        }

        if (c == 15) {
            // ---------------- inline epilogue for tile t ----------------
            const int colbase = (t & 3) * TILE_N + warp_n * 64 + 2 * (lane & 3);
            const int rowbase = (t >> 2) * TILE_M + warp_m * 64 + (lane >> 2);
            #pragma unroll
            for (int ns = 0; ns < 8; ns++) {
                float bx = bias[colbase + ns * 8], by = bias[colbase + ns * 8 + 1];
                #pragma unroll
                for (int ms = 0; ms < 4; ms++) {
                    float* p0 = out + (size_t)(rowbase + ms * 16) * N_TOTAL + colbase + ns * 8;
                    stg_cs_v2(p0, acc[ms][ns][0] + bx, acc[ms][ns][1] + by);
                    float* p1 = p0 + 8 * N_TOTAL;
                    stg_cs_v2(p1, acc[ms][ns][2] + bx, acc[ms][ns][3] + by);
                }
            }
            #pragma unroll
            for (int i = 0; i < 4; i++)
                #pragma unroll
                for (int j = 0; j < 8; j++)
                    #pragma unroll
                    for (int v = 0; v < 4; v++) acc[i][j][v] = 0.f;
            t += GRID_SMS;
        }
    }
}

// ---------------- launch ----------------
extern "C" void kernel_launch(void* const* d_in, const int* in_sizes, int n_in,
                              void* d_out, int out_size) {
    const float* x = (const float*)d_in[0];  // [4, 8192, 1024]
    const float* W = (const float*)d_in[1];  // [1024, 1024]
    const float* b = (const float*)d_in[2];  // [1024]
    float* out = (float*)d_out;              // [4, 8192, 1024]

    absrow_kernel<<<256, 256>>>(W);                                     // idx 0
    alpha_kernel<<<1, 256>>>();                                         // idx 1
    ternarize_kernel<<<(N_TOTAL * K_TOTAL / 8 + 255) / 256, 256>>>(W);  // idx 2

    cudaFuncSetAttribute(gemm_kernel, cudaFuncAttributeMaxDynamicSharedMemorySize, SMEM_TOTAL);
    gemm_kernel<<<GRID_SMS, 256, SMEM_TOTAL>>>(b, x, out);              // idx 3 -> profiled
}

// round 16
// speedup vs baseline: 1.0206x; 1.0206x over previous
#include <cuda_runtime.h>
#include <cuda_fp16.h>
#include <cstdint>

// ---------------- problem sizes ----------------
static constexpr int M_TOTAL = 32768;   // B*S = 4*8192
static constexpr int K_TOTAL = 1024;    // I
static constexpr int N_TOTAL = 1024;    // O
static constexpr int TILE_M  = 128;
static constexpr int TILE_N  = 256;
static constexpr int TILE_K  = 64;
static constexpr int NUM_KC  = K_TOTAL / TILE_K;        // 16
static constexpr int M_TILES = M_TOTAL / TILE_M;        // 256
static constexpr int N_TILES = N_TOTAL / TILE_N;        // 4
static constexpr int NTILES_TOTAL = M_TILES * N_TILES;  // 1024
static constexpr int A_STAGE = TILE_M * TILE_K * 2;     // 16384
static constexpr int B_STAGE = TILE_N * TILE_K * 2;     // 32768
static constexpr int STAGES  = 4;
static constexpr int SMEM_TOTAL = STAGES * (A_STAGE + B_STAGE); // 196608
static constexpr int GRID_SMS = 152;    // GB300 SM count -> persistent 1 CTA/SM

// ---------------- device scratch ----------------
__device__ __align__(16) __half g_wh[(size_t)N_TOTAL * K_TOTAL]; // 2 MiB ternary W f16 row-major
__device__ double g_partial[256];
__device__ float  g_thr;

// ---------------- helpers ----------------
__device__ __forceinline__ uint32_t smem_u32(const void* p) {
    uint32_t a;
    asm("{ .reg .u64 t; cvta.to.shared.u64 t, %1; cvt.u32.u64 %0, t; }" : "=r"(a) : "l"(p));
    return a;
}
__device__ __forceinline__ uint32_t sw128(uint32_t off) { return off ^ ((off >> 3) & 0x70); }

__device__ __forceinline__ void cp_async16(uint32_t smem_addr, const void* gptr) {
    asm volatile("cp.async.cg.shared.global [%0], [%1], 16;"
                 :: "r"(smem_addr), "l"(gptr) : "memory");
}
#define CP_COMMIT() asm volatile("cp.async.commit_group;" ::: "memory")
#define CP_WAIT(n)  asm volatile("cp.async.wait_group %0;" :: "n"(n) : "memory")

__device__ __forceinline__ void ldmatrix_x4(uint32_t* r, uint32_t addr) {
    asm volatile("ldmatrix.sync.aligned.m8n8.x4.shared.b16 {%0,%1,%2,%3}, [%4];"
                 : "=r"(r[0]), "=r"(r[1]), "=r"(r[2]), "=r"(r[3]) : "r"(addr));
}
__device__ __forceinline__ void mma16816(float* d, const uint32_t* a, const uint32_t* b) {
    asm volatile(
        "mma.sync.aligned.m16n8k16.row.col.f32.f16.f16.f32 "
        "{%0,%1,%2,%3}, {%4,%5,%6,%7}, {%8,%9}, {%0,%1,%2,%3};"
        : "+f"(d[0]), "+f"(d[1]), "+f"(d[2]), "+f"(d[3])
        : "r"(a[0]), "r"(a[1]), "r"(a[2]), "r"(a[3]), "r"(b[0]), "r"(b[1]));
}
__device__ __forceinline__ void sts64(uint32_t addr, uint32_t v0, uint32_t v1) {
    asm volatile("st.shared.v2.b32 [%0], {%1,%2};" :: "r"(addr), "r"(v0), "r"(v1) : "memory");
}
__device__ __forceinline__ void stg_cs_v2(float* p, float a, float b) {
    asm volatile("st.global.cs.v2.f32 [%0], {%1,%2};" :: "l"(p), "f"(a), "f"(b) : "memory");
}
// 32B x-load with L2::evict_last (legal shape on this ptxas: .v4.b64).
__device__ __forceinline__ void ldg_el_32B(const float* p, float4& lo, float4& hi) {
    unsigned long long r0, r1, r2, r3;
    asm volatile("ld.global.nc.L2::evict_last.v4.b64 {%0,%1,%2,%3}, [%4];"
                 : "=l"(r0), "=l"(r1), "=l"(r2), "=l"(r3) : "l"(p));
    lo.x = __uint_as_float((uint32_t)r0);  lo.y = __uint_as_float((uint32_t)(r0 >> 32));
    lo.z = __uint_as_float((uint32_t)r1);  lo.w = __uint_as_float((uint32_t)(r1 >> 32));
    hi.x = __uint_as_float((uint32_t)r2);  hi.y = __uint_as_float((uint32_t)(r2 >> 32));
    hi.z = __uint_as_float((uint32_t)r3);  hi.w = __uint_as_float((uint32_t)(r3 >> 32));
}
__device__ __forceinline__ uint32_t f2h2(float a, float b) {
    __half2 h = __floats2half2_rn(a, b);
    return *reinterpret_cast<uint32_t*>(&h);
}

// ---------------- kernel 0: partial |W| sums (deterministic) --------------
__global__ void absrow_kernel(const float* __restrict__ W) {
    __shared__ double sred[256];
    const float4* p = (const float4*)W + blockIdx.x * 1024 + threadIdx.x;
    float s = 0.0f;
    #pragma unroll
    for (int i = 0; i < 4; i++) {
        float4 f = p[i * 256];
        s += fabsf(f.x) + fabsf(f.y) + fabsf(f.z) + fabsf(f.w);
    }
    sred[threadIdx.x] = (double)s;
    __syncthreads();
    for (int off = 128; off > 0; off >>= 1) {
        if (threadIdx.x < off) sred[threadIdx.x] += sred[threadIdx.x + off];
        __syncthreads();
    }
    if (threadIdx.x == 0) g_partial[blockIdx.x] = sred[0];
}

// ---------------- kernel 1: alpha -> g_thr (one block, fixed tree) --------
__global__ void alpha_kernel() {
    __shared__ double sred[256];
    sred[threadIdx.x] = g_partial[threadIdx.x];
    __syncthreads();
    for (int off = 128; off > 0; off >>= 1) {
        if (threadIdx.x < off) sred[threadIdx.x] += sred[threadIdx.x + off];
        __syncthreads();
    }
    if (threadIdx.x == 0) {
        float alpha = (float)(sred[0] / ((double)N_TOTAL * (double)K_TOTAL));
        g_thr = alpha * 0.5f;
    }
}

// ---------------- kernel 2: ternarize W -> f16 row-major -------------------
__global__ void ternarize_kernel(const float* __restrict__ W) {
    float t = g_thr;
    int idx = blockIdx.x * blockDim.x + threadIdx.x;
    if (idx >= N_TOTAL * K_TOTAL / 8) return;
    const float4* src = (const float4*)W + idx * 2;
    uint32_t h[4];
    #pragma unroll
    for (int v = 0; v < 2; v++) {
        float4 f = src[v];
        float q0 = (fabsf(f.x) > t) ? (f.x > 0.f ? 1.f : -1.f) : 0.f;
        float q1 = (fabsf(f.y) > t) ? (f.y > 0.f ? 1.f : -1.f) : 0.f;
        float q2 = (fabsf(f.z) > t) ? (f.z > 0.f ? 1.f : -1.f) : 0.f;
        float q3 = (fabsf(f.w) > t) ? (f.w > 0.f ? 1.f : -1.f) : 0.f;
        h[v * 2]     = f2h2(q0, q1);
        h[v * 2 + 1] = f2h2(q2, q3);
    }
    ((uint4*)g_wh)[idx] = make_uint4(h[0], h[1], h[2], h[3]);
}

// ---------------- kernel 3: PERSISTENT fused-convert f16 mma.sync GEMM ----
// R14 engine EXACTLY (measured 170.6us GEMM, 242 regs): chunk head order is
// issue_B -> kk0 fragment LDSMs -> A-producer LDGs. R15 proved reordering
// LDSMs first pushes regs to 255 and regresses — the allocator dominates.
__global__ void __launch_bounds__(256, 1) gemm_kernel(const float* __restrict__ bias,
                                                      const float* __restrict__ x,
                                                      float* __restrict__ out) {
    extern __shared__ char smem[];
    const int tid = threadIdx.x, lane = tid & 31, wid = tid >> 5;
    const int warp_m = wid & 1;        // 2 warps along M (64 rows)
    const int warp_n = wid >> 1;       // 4 warps along N (64 cols)

    const uint32_t sA = smem_u32(smem);
    const uint32_t sB = sA + STAGES * A_STAGE;

    // ---- affine producer mappings (tile-invariant parts) ----
    const int a_c8 = tid & 7;               // 32B column within 256B fp32 row
    const int a_r0 = tid >> 3;              // 0..31
    const uint32_t a_smem0 = sw128((uint32_t)(a_r0 * 128 + a_c8 * 16)); // +i*4096 swizzle-safe
    const int b_c8 = tid & 7;
    const int b_r0 = tid >> 3;
    const uint32_t b_smem0 = sw128((uint32_t)(b_r0 * 128 + b_c8 * 16)); // +i*4096 swizzle-safe
    const int GROWB = K_TOTAL * 2;

    auto a_base = [&](int t) {
        return x + (size_t)(((t >> 2) * TILE_M) + a_r0) * K_TOTAL + a_c8 * 8;
    };
    auto b_base = [&](int t) {
        return (const char*)(g_wh + (size_t)(((t & 3) * TILE_N) + b_r0) * K_TOTAL) + b_c8 * 16;
    };

    auto issue_B = [&](const char* base, int pc, int s) {
        uint32_t dB = sB + s * B_STAGE + b_smem0;
        const char* srcB = base + pc * (TILE_K * 2);
        #pragma unroll
        for (int i = 0; i < 8; i++)
            cp_async16(dB + i * 4096, srcB + (size_t)i * 32 * GROWB);
        CP_COMMIT();
    };
    auto ldg_A = [&](const float* base, int pc, float4* buf) {
        const float* srcA = base + pc * TILE_K;
        #pragma unroll
        for (int i = 0; i < 4; i++)   // rows a_r0 + 32*i, one 32B load each
            ldg_el_32B(srcA + (size_t)i * 32 * K_TOTAL, buf[i * 2], buf[i * 2 + 1]);
    };
    auto sts_A = [&](int s, const float4* buf) {
        uint32_t dA = sA + s * A_STAGE + a_smem0;
        #pragma unroll
        for (int i = 0; i < 4; i++) {
            sts64(dA + i * 4096,     f2h2(buf[i*2].x, buf[i*2].y), f2h2(buf[i*2].z, buf[i*2].w));
            sts64(dA + i * 4096 + 8, f2h2(buf[i*2+1].x, buf[i*2+1].y), f2h2(buf[i*2+1].z, buf[i*2+1].w));
        }
    };

    // ---- persistent tile bookkeeping ----
    int t = blockIdx.x;                              // current tile
    int pft = t;                                     // tile owning prefetch targets
    const float* pfA = a_base(pft);
    const char*  pfB = b_base(pft);
    const int ntiles = (NTILES_TOTAL - blockIdx.x + GRID_SMS - 1) / GRID_SMS;
    const int total = ntiles * NUM_KC;

    // prologue: chunks 0,1 (lookahead 2) — paid ONCE per CTA
    issue_B(pfB, 0, 0); issue_B(pfB, 1, 1);
    {
        float4 pbuf[8];
        ldg_A(pfA, 0, pbuf); sts_A(0, pbuf);
        ldg_A(pfA, 1, pbuf); sts_A(1, pbuf);
    }

    float acc[4][8][4];
    #pragma unroll
    for (int i = 0; i < 4; i++)
        #pragma unroll
        for (int j = 0; j < 8; j++)
            #pragma unroll
            for (int v = 0; v < 4; v++) acc[i][j][v] = 0.f;

    // ldmatrix lane-address components
    const int a_row = warp_m * 64 + (lane & 15);
    const int a_kof = (lane >> 4) * 8;
    const int b_lrow = warp_n * 64 + (lane & 7) + ((lane >> 4) << 3);
    const int b_kof = ((lane >> 3) & 1) * 8;

    for (int k = 0; k < total; k++) {
        const int c = k & 15;
        if ((k & 1) == 0) {            // barrier every 2nd global chunk
            CP_WAIT(0);
            __syncthreads();
        }

        if (c == 14) {                 // prefetch crosses into next tile
            pft += GRID_SMS;
            if (pft >= NTILES_TOTAL) pft = 0;   // keep pointers valid; unused (pf=false)
            pfA = a_base(pft);
            pfB = b_base(pft);
        }

        const int pk = k + 2;
        const bool pf = (pk < total);
        const int pc = pk & 15;

        const uint32_t aT = sA + (k & 3) * A_STAGE;
        const uint32_t bT = sB + (k & 3) * B_STAGE;

        // 1) B prefetch out first (fire-and-forget; feeds next CP_WAIT)
        if (pf) issue_B(pfB, pc, pk & 3);

        // 2) kk=0 fragments — MMA stream starts ASAP post-barrier
        uint32_t af[4][4], bf[4][4];
        #pragma unroll
        for (int ms = 0; ms < 4; ms++)
            ldmatrix_x4(af[ms], aT + sw128((uint32_t)((a_row + ms * 16) * 128 + a_kof * 2)));
        #pragma unroll
        for (int ns2 = 0; ns2 < 4; ns2++)
            ldmatrix_x4(bf[ns2], bT + sw128((uint32_t)((b_lrow + ns2 * 16) * 128 + b_kof * 2)));

        // 3) A producer LDG batch (independent; overlaps kk=0 MMAs)
        float4 buf[8];
        if (pf) ldg_A(pfA, pc, buf);

        #pragma unroll
        for (int kk = 0; kk < 4; kk++) {
            #pragma unroll
            for (int ms = 0; ms < 4; ms++)
                #pragma unroll
                for (int ns = 0; ns < 8; ns++)
                    mma16816(acc[ms][ns], af[ms], bf[ns >> 1] + (ns & 1) * 2);

            if (kk == 2 && pf)
                sts_A(pk & 3, buf);    // kk==2: ~1560cyc slack for the A LDGs

            if (kk < 3) {              // fragments for kk+1 (same registers)
                #pragma unroll
                for (int ms = 0; ms < 4; ms++)
                    ldmatrix_x4(af[ms], aT + sw128((uint32_t)((a_row + ms * 16) * 128 +
                                                              ((kk + 1) * 16 + a_kof) * 2)));
                #pragma unroll
                for (int ns2 = 0; ns2 < 4; ns2++)
                    ldmatrix_x4(bf[ns2], bT + sw128((uint32_t)((b_lrow + ns2 * 16) * 128 +
                                                               ((kk + 1) * 16 + b_kof) * 2)));
            }
        }

        if (c == 15) {
            // ---------------- inline epilogue for tile t ----------------
            const int colbase = (t & 3) * TILE_N + warp_n * 64 + 2 * (lane & 3);
            const int rowbase = (t >> 2) * TILE_M + warp_m * 64 + (lane >> 2);
            #pragma unroll
            for (int ns = 0; ns < 8; ns++) {
                float bx = bias[colbase + ns * 8], by = bias[colbase + ns * 8 + 1];
                #pragma unroll
                for (int ms = 0; ms < 4; ms++) {
                    float* p0 = out + (size_t)(rowbase + ms * 16) * N_TOTAL + colbase + ns * 8;
                    stg_cs_v2(p0, acc[ms][ns][0] + bx, acc[ms][ns][1] + by);
                    float* p1 = p0 + 8 * N_TOTAL;
                    stg_cs_v2(p1, acc[ms][ns][2] + bx, acc[ms][ns][3] + by);
                }
            }
            #pragma unroll
            for (int i = 0; i < 4; i++)
                #pragma unroll
                for (int j = 0; j < 8; j++)
                    #pragma unroll
                    for (int v = 0; v < 4; v++) acc[i][j][v] = 0.f;
            t += GRID_SMS;
        }
    }
}

// ---------------- launch ----------------
extern "C" void kernel_launch(void* const* d_in, const int* in_sizes, int n_in,
                              void* d_out, int out_size) {
    const float* x = (const float*)d_in[0];  // [4, 8192, 1024]
    const float* W = (const float*)d_in[1];  // [1024, 1024]
    const float* b = (const float*)d_in[2];  // [1024]
    float* out = (float*)d_out;              // [4, 8192, 1024]

    absrow_kernel<<<256, 256>>>(W);                                     // idx 0
    alpha_kernel<<<1, 256>>>();                                         // idx 1
    ternarize_kernel<<<(N_TOTAL * K_TOTAL / 8 + 255) / 256, 256>>>(W);  // idx 2

    cudaFuncSetAttribute(gemm_kernel, cudaFuncAttributeMaxDynamicSharedMemorySize, SMEM_TOTAL);
    gemm_kernel<<<GRID_SMS, 256, SMEM_TOTAL>>>(b, x, out);              // idx 3 -> profiled
}